// round 4
// baseline (speedup 1.0000x reference)
#include <cuda_runtime.h>
#include <math.h>

// ---------------- device scratch ----------------
__device__ float g_blur[4 * 224 * 224 * 256];   // blurred feats, layout [b][y][x][c]
__device__ float g_wp[81 * 256];                // weights repacked [k*9+tap][c]
__device__ int   g_mask_mode;                   // 0=uint8, 1=int32, 2=float32

// ---------------- mask dtype detection ----------------
__global__ void detect_mask_kernel(const unsigned* __restrict__ m) {
    int lane = threadIdx.x;  // 32 threads
    int fcount = 0, zocount = 0;
#pragma unroll
    for (int i = 0; i < 8; i++) {
        unsigned w = m[lane * 8 + i];
        if (w == 0x3f800000u) fcount++;
        if (w <= 1u) zocount++;
    }
#pragma unroll
    for (int o = 16; o; o >>= 1) {
        fcount  += __shfl_xor_sync(0xffffffffu, fcount, o);
        zocount += __shfl_xor_sync(0xffffffffu, zocount, o);
    }
    if (lane == 0) g_mask_mode = (fcount > 0) ? 2 : ((zocount == 256) ? 1 : 0);
}

// ---------------- weight repack: (9,256,3,3) -> [k*9+tap][c] ----------------
__global__ void repack_kernel(const float* __restrict__ ak) {
    int idx = blockIdx.x * 256 + threadIdx.x;  // 81 blocks * 256 = 20736
    int c  = idx & 255;
    int kt = idx >> 8;           // k*9 + tap, 0..80
    int k = kt / 9, tap = kt - k * 9;
    g_wp[idx] = ak[(k * 256 + c) * 9 + tap];
}

// ---------------- separable 5x5 gaussian blur ----------------
// CTA: 32 channels x 16y x 32x tile, 512 threads, vertical-first rolling pass.
// occupancy 3 (3 x 75.9KB smem = 227.7KB)
#define BLUR_SMEM (32 * 593 * 4)

__global__ void __launch_bounds__(512, 3) blur_kernel(const float* __restrict__ hr) {
    extern __shared__ float s_v[];

    const float C = -1.4142135623730951f;
    float tb[5]; float s = 0.f;
#pragma unroll
    for (int j = 0; j < 5; j++) { float d = (float)(j - 2); tb[j] = expf(d * d * C); s += tb[j]; }
#pragma unroll
    for (int j = 0; j < 5; j++) tb[j] = tb[j] / s;

    int b = blockIdx.z, cb = blockIdx.y;
    int tx = blockIdx.x % 7, ty = blockIdx.x / 7;
    int x0 = tx * 32, y0 = ty * 16;
    int t = threadIdx.x;

    // phase 1: vertical blur, rolling window per column. 1152 columns (32ch x 36x)
    for (int j = t; j < 1152; j += 512) {
        int ch = j / 36, lx = j - ch * 36;
        int ix = x0 - 2 + lx;
        bool vx = (ix >= 0 && ix < 224);
        const float* base = hr + ((long)(b * 256 + cb * 32 + ch) * 224) * 224 + ix;
        float w0 = 0.f, w1 = 0.f, w2 = 0.f, w3 = 0.f, w4 = 0.f;
        float* ov = s_v + ch * 593 + lx;
#pragma unroll
        for (int yy = 0; yy < 20; yy++) {
            int iy = y0 - 2 + yy;
            float v = (vx && iy >= 0 && iy < 224) ? base[iy * 224] : 0.f;
            w0 = w1; w1 = w2; w2 = w3; w3 = w4; w4 = v;
            if (yy >= 4) {
                float o = w0*tb[0] + w1*tb[1] + w2*tb[2] + w3*tb[3] + w4*tb[4];
                ov[(yy - 4) * 37] = o;
            }
        }
    }
    __syncthreads();

    // phase 2: horizontal blur + transposed store (lane = channel -> 128B stores)
    {
        int ch = t & 31, yr = t >> 5;   // yr 0..15
        const float* vp = s_v + ch * 593 + yr * 37;
        float* ob = g_blur + ((long)(b * 224 + y0 + yr) * 224 + x0) * 256 + cb * 32 + ch;
        float a0 = vp[0], a1 = vp[1], a2 = vp[2], a3 = vp[3];
#pragma unroll
        for (int x = 0; x < 32; x++) {
            float a4 = vp[x + 4];
            float o = a0*tb[0] + a1*tb[1] + a2*tb[2] + a3*tb[3] + a4*tb[4];
            ob[x * 256] = o;
            a0 = a1; a1 = a2; a2 = a3; a3 = a4;
        }
    }
}

// ---------------- fused logits + softmax + einsum v3 ----------------
// CTA: 2x8 output tile, 512 threads.
// s_blur: 5x17 region, parity-split rows, 85 rows x 260 floats:
//   even rix: row = riy*9 + rix/2      (45 rows)
//   odd  rix: row = 45 + riy*8 + rix/2 (40 rows)
// phase B: thread = (c2 = t&127 [float2 channels], pq = t>>7 [pixel quarter])
//   pq: py = pq>>1, xh = pq&1; pixels px = 4*xh + i, i=0..3
//   acc[9][4], weights streamed via __ldg float2 (p=4 blocking halves w traffic)
// smem floats: s_blur 22100 | s_red 576 | s_logit 144 | s_attn 144
#define FUSED_SMEM ((22100 + 576 + 144 + 144) * 4)

__global__ void __launch_bounds__(512, 2) fused_kernel(
    const void* __restrict__ maskp,
    const float* __restrict__ kbias,
    const float* __restrict__ lbias,
    float* __restrict__ out)
{
    extern __shared__ float sm[];
    float* s_blur  = sm;             // 22100
    float* s_red   = sm + 22100;     // 576
    float* s_logit = sm + 22676;     // 144
    float* s_attn  = sm + 22820;     // 144

    int t = threadIdx.x;
    int b = blockIdx.z;
    int x0o = blockIdx.x * 8, y0o = blockIdx.y * 2;
    int rx0 = 2 * x0o - 1, ry0 = 2 * y0o - 1;

    // ---- load 5x17 blurred region (85 rows x 256ch) ----
    {
        int c4 = t & 63, rr = t >> 6;   // 8 row-streams
        const float* gb = g_blur + (long)b * 224 * 224 * 256 + c4 * 4;
        for (int row = rr; row < 85; row += 8) {
            int riy, rix;
            if (row < 45) { riy = row / 9;  rix = 2 * (row - riy * 9); }
            else { int q = row - 45; riy = q >> 3; rix = 2 * (q & 7) + 1; }
            int iy = ry0 + riy, ix = rx0 + rix;
            float4 v = make_float4(0.f, 0.f, 0.f, 0.f);
            if (iy >= 0 && iy < 224 && ix >= 0 && ix < 224)
                v = *(const float4*)(gb + ((long)iy * 224 + ix) * 256);
            *(float4*)(s_blur + row * 260 + c4 * 4) = v;
        }
    }
    __syncthreads();

    // ---- phase B: logits. thread = (c2, pq), 4 pixels x 9 k each ----
    {
        int c2 = t & 127, pq = t >> 7;
        int py = pq >> 1, xh = pq & 1;
        const float2* sb2 = (const float2*)s_blur;   // row stride 130 float2
        const float2* wp2 = (const float2*)g_wp;     // kt stride 128 float2

        float acc[9][4];
#pragma unroll
        for (int k = 0; k < 9; k++)
#pragma unroll
            for (int i = 0; i < 4; i++) acc[k][i] = 0.f;

#pragma unroll
        for (int dy = 0; dy < 3; dy++) {
            int riy = 2 * py + dy;
            int re = riy * 9 + 4 * xh;        // even-rix base for dx=0
            int ro = 45 + riy * 8 + 4 * xh;   // odd-rix base
#pragma unroll
            for (int dx = 0; dx < 3; dx++) {
                int rbase = (dx == 1) ? ro : (re + (dx >> 1));
                float2 v0 = sb2[(rbase + 0) * 130 + c2];
                float2 v1 = sb2[(rbase + 1) * 130 + c2];
                float2 v2 = sb2[(rbase + 2) * 130 + c2];
                float2 v3 = sb2[(rbase + 3) * 130 + c2];
                int tap = dy * 3 + dx;
#pragma unroll
                for (int k = 0; k < 9; k++) {
                    float2 w = __ldg(&wp2[(k * 9 + tap) * 128 + c2]);
                    acc[k][0] = fmaf(v0.y, w.y, fmaf(v0.x, w.x, acc[k][0]));
                    acc[k][1] = fmaf(v1.y, w.y, fmaf(v1.x, w.x, acc[k][1]));
                    acc[k][2] = fmaf(v2.y, w.y, fmaf(v2.x, w.x, acc[k][2]));
                    acc[k][3] = fmaf(v3.y, w.y, fmaf(v3.x, w.x, acc[k][3]));
                }
            }
        }

        // warp butterfly over the 32 c2-lanes (pure channel reduction)
#pragma unroll
        for (int o = 16; o; o >>= 1)
#pragma unroll
            for (int k = 0; k < 9; k++) {
                acc[k][0] += __shfl_xor_sync(0xffffffffu, acc[k][0], o);
                acc[k][1] += __shfl_xor_sync(0xffffffffu, acc[k][1], o);
                acc[k][2] += __shfl_xor_sync(0xffffffffu, acc[k][2], o);
                acc[k][3] += __shfl_xor_sync(0xffffffffu, acc[k][3], o);
            }
        int w = t >> 5, lane = t & 31;
        if (lane == 0) {
#pragma unroll
            for (int k = 0; k < 9; k++)
#pragma unroll
                for (int i = 0; i < 4; i++)
                    s_red[w * 36 + k * 4 + i] = acc[k][i];
        }
    }
    __syncthreads();

    // ---- combine 4 warp-partials + bias -> logits ----
    if (t < 144) {
        int p = t / 9, k = t - p * 9;
        int py = p >> 3, px = p & 7;
        int pq = py * 2 + (px >> 2), i = px & 3;
        float v = kbias[k];
#pragma unroll
        for (int ws = 0; ws < 4; ws++)
            v += s_red[(pq * 4 + ws) * 36 + k * 4 + i];
        s_logit[p * 9 + k] = v;
    }
    __syncthreads();

    // ---- softmax over 9 with keep_mask + logit_bias ----
    if (t < 16) {
        int p = t;
        int oy = y0o + (p >> 3), ox = x0o + (p & 7);
        int mm = g_mask_mode;
        float lg[9];
#pragma unroll
        for (int k = 0; k < 9; k++) {
            long midx = ((long)(b * 9 + k) * 112 + oy) * 112 + ox;
            bool keep;
            if (mm == 0)      keep = ((const unsigned char*)maskp)[midx] != 0;
            else if (mm == 1) keep = ((const int*)maskp)[midx] != 0;
            else              keep = ((const float*)maskp)[midx] != 0.f;
            lg[k] = (keep ? s_logit[p * 9 + k] : 0.f) + lbias[k];
        }
        float mx = lg[0];
#pragma unroll
        for (int k = 1; k < 9; k++) mx = fmaxf(mx, lg[k]);
        float e[9]; float ssum = 0.f;
#pragma unroll
        for (int k = 0; k < 9; k++) { e[k] = expf(lg[k] - mx); ssum += e[k]; }
        float invs = 1.0f / ssum;
#pragma unroll
        for (int k = 0; k < 9; k++) s_attn[p * 9 + k] = e[k] * invs;
    }
    __syncthreads();

    // ---- einsum: thread = (c in 0..255, r in 0..1), 8 x-outputs each ----
    {
        int c = t & 255, r = t >> 8;
        float ox[8];
#pragma unroll
        for (int x = 0; x < 8; x++) ox[x] = 0.f;
#pragma unroll
        for (int dy = 0; dy < 3; dy++) {
            int riy = 2 * r + dy;
#pragma unroll
            for (int dx = 0; dx < 3; dx++) {
                int k = dy * 3 + dx;
#pragma unroll
                for (int x = 0; x < 8; x++) {
                    int rix = 2 * x + dx;
                    int row = (rix & 1) ? (45 + riy * 8 + (rix >> 1))
                                        : (riy * 9 + (rix >> 1));
                    float v = s_blur[row * 260 + c];
                    float a = s_attn[(r * 8 + x) * 9 + k];
                    ox[x] = fmaf(v, a, ox[x]);
                }
            }
        }
        float* ob = out + ((long)(b * 256 + c) * 112 + y0o + r) * 112 + x0o;
        *(float4*)(ob)     = make_float4(ox[0], ox[1], ox[2], ox[3]);
        *(float4*)(ob + 4) = make_float4(ox[4], ox[5], ox[6], ox[7]);
    }
}

// ---------------- launch ----------------
extern "C" void kernel_launch(void* const* d_in, const int* in_sizes, int n_in,
                              void* d_out, int out_size) {
    const float* hr  = (const float*)d_in[0];
    const float* ak  = (const float*)d_in[1];
    const float* kb  = (const float*)d_in[2];
    const float* lb  = (const float*)d_in[3];
    const void*  msk = d_in[4];
    float* out = (float*)d_out;
    (void)in_sizes; (void)n_in; (void)out_size;

    cudaFuncSetAttribute(blur_kernel,  cudaFuncAttributeMaxDynamicSharedMemorySize, BLUR_SMEM);
    cudaFuncSetAttribute(fused_kernel, cudaFuncAttributeMaxDynamicSharedMemorySize, FUSED_SMEM);

    detect_mask_kernel<<<1, 32>>>((const unsigned*)msk);
    repack_kernel<<<81, 256>>>(ak);
    blur_kernel<<<dim3(98, 8, 4), 512, BLUR_SMEM>>>(hr);
    fused_kernel<<<dim3(14, 56, 4), 512, FUSED_SMEM>>>(msk, kb, lb, out);
}